// round 16
// baseline (speedup 1.0000x reference)
#include <cuda_runtime.h>
#include <cuda_fp16.h>
#include <cstdint>

// N=8192 tokens, D=128, x layout [8,384,32,32] fp32 (feature-major)
#define NTILES 64
#define SCALE 0.08838834764831845f  // 1/sqrt(128)

// byte offsets in dynamic smem; all fp16 tiles row=256B, XOR-swizzled 16B units
#define QB    0u        // Q  [m 64][k=feat 128]
#define KAB   16384u    // K group A
#define KBB   49152u    // K group B
#define VAB   81920u    // V group A
#define VBB   114688u   // V group B
#define PA0B  147456u   // P group A, slot 0
#define PA1B  163840u   // P group A, slot 1
#define PB0B  180224u   // P group B, slot 0
#define PB1B  196608u   // P group B, slot 1
#define SMEM_BYTES 214272
#define RS4W  53248     // word idx: 64 x 4 partial rowsums (A0,A1,B0,B1)
#define RSW   53504     // word idx: 64 inverse rowsums
#define OCW   4096      // word idx: epilogue O-combine scratch (reuses K buffers)
#define OST   68        // O-combine row stride (floats)

// barrier ids:
//  0: __syncthreads
//  1+g01        (128): K staged-visible / readers-done (2 rendezvous per iter)
//  3+g01        (128): V staged-visible / readers-done
//  5+g01*2+slot (256): P(slot) full   (S arrives, PV syncs)
//  9+g01*2+slot (256): P(slot) free   (PV arrives, S syncs from 2nd use)

// one-time fp16 scratch (prepass output)
__device__ __half g_kt[8192 * 128];      // K^T: [token][feature]
__device__ __half g_v[8 * 128 * 1024];   // V:   [batch][feature][token]

extern __shared__ float smdyn[];

__device__ __forceinline__ uint32_t smem_u32(const void* p) {
    uint32_t a;
    asm("{ .reg .u64 t; cvta.to.shared.u64 t, %1; cvt.u32.u64 %0, t; }" : "=r"(a) : "l"(p));
    return a;
}
__device__ __forceinline__ void bar_sync(int id, int cnt) {
    asm volatile("bar.sync %0, %1;" :: "r"(id), "r"(cnt) : "memory");
}
__device__ __forceinline__ void bar_arrive(int id, int cnt) {
    asm volatile("bar.arrive %0, %1;" :: "r"(id), "r"(cnt) : "memory");
}
__device__ __forceinline__ uint32_t h2bits(float a, float b) {
    __half2 h = __floats2half2_rn(a, b);
    return *reinterpret_cast<uint32_t*>(&h);
}
__device__ __forceinline__ float h2sum(uint32_t u) {
    __half2 h = *reinterpret_cast<__half2*>(&u);
    float2 f = __half22float2(h);
    return f.x + f.y;
}
__device__ __forceinline__ void sts128(uint32_t a, uint32_t u0, uint32_t u1,
                                       uint32_t u2, uint32_t u3) {
    asm volatile("st.shared.v4.b32 [%0], {%1,%2,%3,%4};"
                 :: "r"(a), "r"(u0), "r"(u1), "r"(u2), "r"(u3) : "memory");
}
__device__ __forceinline__ void sts32(uint32_t a, uint32_t u0) {
    asm volatile("st.shared.b32 [%0], %1;" :: "r"(a), "r"(u0) : "memory");
}
__device__ __forceinline__ void ldsm4(uint32_t r[4], uint32_t addr) {
    asm volatile("ldmatrix.sync.aligned.m8n8.x4.shared.b16 {%0,%1,%2,%3}, [%4];"
                 : "=r"(r[0]), "=r"(r[1]), "=r"(r[2]), "=r"(r[3]) : "r"(addr));
}
__device__ __forceinline__ void mma16(float c[4], const uint32_t a[4], const uint32_t b[2]) {
    asm volatile("mma.sync.aligned.m16n8k16.row.col.f32.f16.f16.f32 "
                 "{%0,%1,%2,%3}, {%4,%5,%6,%7}, {%8,%9}, {%0,%1,%2,%3};"
                 : "+f"(c[0]), "+f"(c[1]), "+f"(c[2]), "+f"(c[3])
                 : "r"(a[0]), "r"(a[1]), "r"(a[2]), "r"(a[3]),
                   "r"(b[0]), "r"(b[1]));
}
__device__ __forceinline__ void cp16h(uint32_t dst, const __half* src) {
    asm volatile("cp.async.cg.shared.global [%0], [%1], 16;" :: "r"(dst), "l"(src));
}
__device__ __forceinline__ void cp_commit() { asm volatile("cp.async.commit_group;"); }
__device__ __forceinline__ void cp_wait0()  { asm volatile("cp.async.wait_group 0;"); }

// ================= prepass: x fp32 -> fp16 scratch (K transposed) =================
__global__ void __launch_bounds__(256) prepass_kernel(const float* __restrict__ x) {
    const int tid  = blockIdx.x * 256 + threadIdx.x;   // 0..16383
    const int wid  = tid >> 5;                          // 0..511
    const int lane = threadIdx.x & 31;

#pragma unroll
    for (int i = 0; i < 8; i++) {
        int job = wid * 8 + i;
        int tb = job >> 4, fg = job & 15;
        int b = tb >> 5;
        int t = (tb & 31) * 32 + lane;
        const float* gp = x + (size_t)b * 393216u + (size_t)(128 + fg * 8) * 1024u + t;
        float f[8];
#pragma unroll
        for (int j = 0; j < 8; j++) f[j] = gp[(size_t)j * 1024];
        uint4 u;
        u.x = h2bits(f[0], f[1]); u.y = h2bits(f[2], f[3]);
        u.z = h2bits(f[4], f[5]); u.w = h2bits(f[6], f[7]);
        *(uint4*)(&g_kt[(size_t)((b * 1024 + t) * 128 + fg * 8)]) = u;
    }
#pragma unroll
    for (int i = 0; i < 8; i++) {
        int e = (i * 16384 + tid) * 8;
        int b = e >> 17;
        int r = e & 131071;
        const float* gp = x + (size_t)b * 393216u + r;
        float4 a0 = *(const float4*)gp;
        float4 a1 = *(const float4*)(gp + 4);
        uint4 u;
        u.x = h2bits(a0.x, a0.y); u.y = h2bits(a0.z, a0.w);
        u.z = h2bits(a1.x, a1.y); u.w = h2bits(a1.z, a1.w);
        *(uint4*)(&g_v[e]) = u;
    }
}

// ---- staging: cp.async fp16 scratch -> swizzled smem (4 warps per array) ----
__device__ __forceinline__ void stage_K_async(int kt, uint32_t skb, int pr, int lane) {
#pragma unroll
    for (int i = 0; i < 16; i++) {
        int id = pr * 512 + i * 32 + lane;      // 0..2047 16B-units
        int n = id >> 4, fg = id & 15;
        cp16h(skb + (uint32_t)(n * 256 + ((fg ^ (n & 7)) << 4)),
              g_kt + (size_t)((kt * 128 + n) * 128 + fg * 8));
    }
}
__device__ __forceinline__ void stage_V_async(int kt, uint32_t svb, int pr, int lane) {
    const int bv = kt >> 3, tof = (kt & 7) << 7;
#pragma unroll
    for (int i = 0; i < 16; i++) {
        int id = pr * 512 + i * 32 + lane;
        int v = id >> 4, u = id & 15;
        cp16h(svb + (uint32_t)(v * 256 + ((u ^ (v & 7)) << 4)),
              g_v + (size_t)((bv * 128 + v) * 1024 + tof + u * 8));
    }
}

__global__ void __launch_bounds__(512, 1)
conv_attn_kernel(const float* __restrict__ x, float* __restrict__ out) {
    const int tid  = threadIdx.x;
    const int lane = tid & 31;
    const int wid  = tid >> 5;
    const int g    = lane >> 2;
    const int t4   = lane & 3;
    const uint32_t sb = smem_u32(smdyn);
    float* smf = smdyn;

    const int g01  = wid >> 3;                 // 0 = group A (even kt), 1 = B (odd kt)
    const int w4   = wid & 3;
    const bool isS = (wid & 7) < 4;

    const int bq  = blockIdx.x >> 4;
    const int sq0 = (blockIdx.x & 15) << 6;
    const float* Qg = x + (size_t)bq * 393216u + 262144u + sq0;

    // ldmatrix per-lane decomposition
    const int rowoff  = ((lane >> 3) & 1) * 8 + (lane & 7);  // A rows
    const int selA    = lane >> 4;                           // A k-half
    const int rowoffB = (lane >> 4) * 8 + (lane & 7);        // B rows
    const int selB    = (lane >> 3) & 1;                     // B k-half
    const int sw      = lane & 7;

    const uint32_t sKg   = sb + (g01 ? KBB : KAB);
    const uint32_t sVg   = sb + (g01 ? VBB : VAB);
    const uint32_t sPgrp = sb + (g01 ? PB0B : PA0B);   // + slot<<14

    // ---- prologue: all warps stage Q; S warps cp K(g01); PV warps cp V(g01) ----
#pragma unroll
    for (int it = 0; it < 2; it++) {
        int job = wid + 16 * it;                 // 32 jobs: tg 0..1 x fg 0..15
        int tg = job >> 4, fg = job & 15;
        int m = tg * 32 + lane;
        const float* gp = Qg + (size_t)(fg * 8) * 1024 + m;
        float f[8];
#pragma unroll
        for (int j = 0; j < 8; j++) f[j] = gp[(size_t)j * 1024];
        uint32_t a = sb + QB + (uint32_t)(m * 256 + ((fg ^ (m & 7)) << 4));
        sts128(a, h2bits(f[0], f[1]), h2bits(f[2], f[3]),
                  h2bits(f[4], f[5]), h2bits(f[6], f[7]));
    }
    if (isS) { stage_K_async(g01, sKg, w4, lane); cp_commit(); }
    else     { stage_V_async(g01, sVg, w4, lane); cp_commit(); }
    __syncthreads();

    if (isS) {
        // ===== S warps (32x64 tiles, split into two 32-col halves): =====
        // half0 mma -> [half1 mma interleaved with softmax(half0)] -> softmax(half1)
        const int qrow = (w4 >> 1) * 32;
        const int scol = (w4 & 1) * 64;
        const uint32_t qa0 = sb + QB + (uint32_t)((qrow + rowoff) * 256);
        const uint32_t qa1 = qa0 + 16 * 256;
        const uint32_t kb  = sKg + (uint32_t)((scol + rowoffB) * 256);
        const int row0 = qrow + g;              // mt=0 row
        const int row1 = qrow + 16 + g;         // mt=1 row
        float racc0[2] = {0.f, 0.f}, racc1[2] = {0.f, 0.f};

        for (int kt = g01; kt < NTILES; kt += 2) {
            const int slot = (kt >> 1) & 1;
            cp_wait0();
            bar_sync(1 + g01, 128);              // K(kt) visible (rendezvous 1)

            float c0[2][4][4], c1[2][4][4];
#pragma unroll
            for (int mt = 0; mt < 2; mt++)
#pragma unroll
                for (int nt = 0; nt < 4; nt++)
#pragma unroll
                    for (int r = 0; r < 4; r++) { c0[mt][nt][r] = 0.f; c1[mt][nt][r] = 0.f; }

            // ---- half 0 mma (cols scol .. scol+31) ----
#pragma unroll
            for (int ks = 0; ks < 8; ks++) {
                const uint32_t ua = (uint32_t)(((2 * ks + selA) ^ sw) << 4);
                const uint32_t ub = (uint32_t)(((2 * ks + selB) ^ sw) << 4);
                uint32_t a0[4], a1[4], b[2][4];
                ldsm4(a0, qa0 + ua);
                ldsm4(a1, qa1 + ua);
                ldsm4(b[0], kb + ub);
                ldsm4(b[1], kb + 16 * 256 + ub);
#pragma unroll
                for (int nb = 0; nb < 2; nb++) {
                    mma16(c0[0][2 * nb],     a0, b[nb] + 0);
                    mma16(c0[0][2 * nb + 1], a0, b[nb] + 2);
                    mma16(c0[1][2 * nb],     a1, b[nb] + 0);
                    mma16(c0[1][2 * nb + 1], a1, b[nb] + 2);
                }
            }

            if (kt >= 4) bar_sync(9 + g01 * 2 + slot, 256);  // P slot free (PV(kt-4) done)
            const uint32_t sPg = sPgrp + (uint32_t)(slot << 14);

            float s00 = 0.f, s01 = 0.f, s10 = 0.f, s11 = 0.f;

            // ---- half 1 mma (cols scol+32 .. scol+63) interleaved with softmax(c0) ----
#pragma unroll
            for (int ks = 0; ks < 8; ks++) {
                const uint32_t ua = (uint32_t)(((2 * ks + selA) ^ sw) << 4);
                const uint32_t ub = (uint32_t)(((2 * ks + selB) ^ sw) << 4);
                uint32_t a0[4], a1[4], b[2][4];
                ldsm4(a0, qa0 + ua);
                ldsm4(a1, qa1 + ua);
                ldsm4(b[0], kb + 32 * 256 + ub);
                ldsm4(b[1], kb + 48 * 256 + ub);
#pragma unroll
                for (int nb = 0; nb < 2; nb++) {
                    mma16(c1[0][2 * nb],     a0, b[nb] + 0);
                    mma16(c1[0][2 * nb + 1], a0, b[nb] + 2);
                    mma16(c1[1][2 * nb],     a1, b[nb] + 0);
                    mma16(c1[1][2 * nb + 1], a1, b[nb] + 2);
                }
                // softmax piece of c0: ks 0..3 -> mt0 nt0..3 ; ks 4..7 -> mt1 nt0..3
                {
                    const int mt = ks >> 2, nt = ks & 3;
                    float e0 = __expf(c0[mt][nt][0] * SCALE);
                    float e1 = __expf(c0[mt][nt][1] * SCALE);
                    float e2 = __expf(c0[mt][nt][2] * SCALE);
                    float e3 = __expf(c0[mt][nt][3] * SCALE);
                    uint32_t u01 = h2bits(e0, e1);
                    uint32_t u23 = h2bits(e2, e3);
                    if (mt == 0) { s00 += h2sum(u01); s01 += h2sum(u23); }
                    else         { s10 += h2sum(u01); s11 += h2sum(u23); }
                    const int unit = (scol >> 3) + nt;
                    const int row = (mt ? row1 : row0);
                    sts32(sPg + (uint32_t)(row * 256 + ((unit ^ g) << 4) + 4 * t4), u01);
                    sts32(sPg + (uint32_t)((row + 8) * 256 + ((unit ^ g) << 4) + 4 * t4), u23);
                }
            }

            bar_sync(1 + g01, 128);              // K readers done (rendezvous 2)
            if (kt + 2 < NTILES) { stage_K_async(kt + 2, sKg, w4, lane); cp_commit(); }

            // ---- softmax(c1): cols scol+32..63 (nt 4..7) ----
#pragma unroll
            for (int mt = 0; mt < 2; mt++) {
#pragma unroll
                for (int nt = 0; nt < 4; nt++) {
                    float e0 = __expf(c1[mt][nt][0] * SCALE);
                    float e1 = __expf(c1[mt][nt][1] * SCALE);
                    float e2 = __expf(c1[mt][nt][2] * SCALE);
                    float e3 = __expf(c1[mt][nt][3] * SCALE);
                    uint32_t u01 = h2bits(e0, e1);
                    uint32_t u23 = h2bits(e2, e3);
                    if (mt == 0) { s00 += h2sum(u01); s01 += h2sum(u23); }
                    else         { s10 += h2sum(u01); s11 += h2sum(u23); }
                    const int unit = (scol >> 3) + 4 + nt;
                    const int row = (mt ? row1 : row0);
                    sts32(sPg + (uint32_t)(row * 256 + ((unit ^ g) << 4) + 4 * t4), u01);
                    sts32(sPg + (uint32_t)((row + 8) * 256 + ((unit ^ g) << 4) + 4 * t4), u23);
                }
            }
            // rowsum shfl reduction (same order as before: mt0 then mt1)
            s00 += __shfl_xor_sync(0xffffffffu, s00, 1);
            s00 += __shfl_xor_sync(0xffffffffu, s00, 2);
            s01 += __shfl_xor_sync(0xffffffffu, s01, 1);
            s01 += __shfl_xor_sync(0xffffffffu, s01, 2);
            racc0[0] += s00; racc1[0] += s01;
            s10 += __shfl_xor_sync(0xffffffffu, s10, 1);
            s10 += __shfl_xor_sync(0xffffffffu, s10, 2);
            s11 += __shfl_xor_sync(0xffffffffu, s11, 1);
            s11 += __shfl_xor_sync(0xffffffffu, s11, 2);
            racc0[1] += s10; racc1[1] += s11;

            bar_arrive(5 + g01 * 2 + slot, 256); // P(kt) full
        }

        if (t4 == 0) {
#pragma unroll
            for (int mt = 0; mt < 2; mt++) {
                const int row = qrow + mt * 16 + g;
                smf[RS4W + row * 4 + g01 * 2 + (w4 & 1)]       = racc0[mt];
                smf[RS4W + (row + 8) * 4 + g01 * 2 + (w4 & 1)] = racc1[mt];
            }
        }
        __syncthreads();                          // epilogue join (1)
        if (tid < 64) {
            const float* r4 = smf + RS4W + tid * 4;
            smf[RSW + tid] = 1.0f / ((r4[0] + r4[1]) + (r4[2] + r4[3]));
        }
        __syncthreads();                          // epilogue join (2)
    } else {
        // ===== PV warps (64x32 tiles): O^T += V P^T over group's kt =====
        const int vrow = (w4 >> 1) * 64;
        const int mcol = (w4 & 1) * 32;
        const uint32_t va    = sVg + (uint32_t)((vrow + rowoff) * 256);
        const uint32_t pboff = (uint32_t)((mcol + rowoffB) * 256);

        float o[4][4][4];
#pragma unroll
        for (int a = 0; a < 4; a++)
#pragma unroll
            for (int b = 0; b < 4; b++)
#pragma unroll
                for (int r = 0; r < 4; r++) o[a][b][r] = 0.f;

        for (int kt = g01; kt < NTILES; kt += 2) {
            const int slot = (kt >> 1) & 1;
            bar_sync(5 + g01 * 2 + slot, 256);   // P(kt) full
            cp_wait0();
            bar_sync(3 + g01, 128);              // V(kt) visible (rendezvous 1)

            const uint32_t pbb = sPgrp + (uint32_t)(slot << 14) + pboff;
#pragma unroll
            for (int ks = 0; ks < 8; ks++) {
                const uint32_t ua = (uint32_t)(((2 * ks + selA) ^ sw) << 4);
                const uint32_t ub = (uint32_t)(((2 * ks + selB) ^ sw) << 4);
                uint32_t a[4][4], b0[4];
                ldsm4(a[0], va + ua);
                ldsm4(a[1], va + 16 * 256 + ua);
                ldsm4(a[2], va + 32 * 256 + ua);
                ldsm4(a[3], va + 48 * 256 + ua);
                ldsm4(b0, pbb + ub);
#pragma unroll
                for (int vt = 0; vt < 4; vt++) {
                    mma16(o[vt][0], a[vt], b0 + 0);
                    mma16(o[vt][1], a[vt], b0 + 2);
                }
                uint32_t b1[4];
                ldsm4(b1, pbb + 16 * 256 + ub);
#pragma unroll
                for (int vt = 0; vt < 4; vt++) {
                    mma16(o[vt][2], a[vt], b1 + 0);
                    mma16(o[vt][3], a[vt], b1 + 2);
                }
            }
            bar_arrive(9 + g01 * 2 + slot, 256); // P(kt) slot free
            bar_sync(3 + g01, 128);              // V readers done (rendezvous 2)
            if (kt + 2 < NTILES) { stage_V_async(kt + 2, sVg, w4, lane); cp_commit(); }
        }

        __syncthreads();                          // epilogue join (1)
        if (g01 == 0) {
            // group A: park partial O in smem (K buffers are dead now)
#pragma unroll
            for (int bn = 0; bn < 4; bn++) {
                const int m0 = mcol + bn * 8 + 2 * t4;
#pragma unroll
                for (int vt = 0; vt < 4; vt++) {
                    const int v = vrow + vt * 16 + g;
                    *(float2*)(smf + OCW + v * OST + m0) =
                        make_float2(o[vt][bn][0], o[vt][bn][1]);
                    *(float2*)(smf + OCW + (v + 8) * OST + m0) =
                        make_float2(o[vt][bn][2], o[vt][bn][3]);
                }
            }
        }
        __syncthreads();                          // epilogue join (2)
        if (g01 == 1) {
            // group B: combine + normalize + store
            float* Og = out + (size_t)bq * 131072u + sq0;
#pragma unroll
            for (int bn = 0; bn < 4; bn++) {
                const int m0 = mcol + bn * 8 + 2 * t4;
                const float i0 = smf[RSW + m0], i1 = smf[RSW + m0 + 1];
#pragma unroll
                for (int vt = 0; vt < 4; vt++) {
                    const int v = vrow + vt * 16 + g;
                    float2 a0 = *(const float2*)(smf + OCW + v * OST + m0);
                    float2 a1 = *(const float2*)(smf + OCW + (v + 8) * OST + m0);
                    *(float2*)(Og + (size_t)v * 1024 + m0) =
                        make_float2((a0.x + o[vt][bn][0]) * i0,
                                    (a0.y + o[vt][bn][1]) * i1);
                    *(float2*)(Og + (size_t)(v + 8) * 1024 + m0) =
                        make_float2((a1.x + o[vt][bn][2]) * i0,
                                    (a1.y + o[vt][bn][3]) * i1);
                }
            }
        }
    }
}

extern "C" void kernel_launch(void* const* d_in, const int* in_sizes, int n_in,
                              void* d_out, int out_size) {
    (void)in_sizes; (void)n_in; (void)out_size;
    const float* x = (const float*)d_in[0];
    float* out = (float*)d_out;
    cudaFuncSetAttribute(conv_attn_kernel,
                         cudaFuncAttributeMaxDynamicSharedMemorySize, SMEM_BYTES);
    prepass_kernel<<<64, 256>>>(x);
    conv_attn_kernel<<<128, 512, SMEM_BYTES>>>(x, out);
}

// round 17
// speedup vs baseline: 1.0313x; 1.0313x over previous
#include <cuda_runtime.h>
#include <cuda_fp16.h>
#include <cstdint>

// N=8192 tokens, D=128, x layout [8,384,32,32] fp32 (feature-major)
#define NTILES 64
#define SCALE 0.08838834764831845f  // 1/sqrt(128)

// byte offsets in dynamic smem; all fp16 tiles row=256B, XOR-swizzled 16B units
#define QB    0u        // Q  [m 64][k=feat 128]
#define KAB   16384u    // K group A
#define KBB   49152u    // K group B
#define VAB   81920u    // V group A
#define VBB   114688u   // V group B
#define PA0B  147456u   // P group A, slot 0
#define PA1B  163840u   // P group A, slot 1
#define PB0B  180224u   // P group B, slot 0
#define PB1B  196608u   // P group B, slot 1
#define SMEM_BYTES 214272
#define RS4W  53248     // word idx: 64 x 4 partial rowsums (A0,A1,B0,B1)
#define RSW   53504     // word idx: 64 inverse rowsums
#define OCW   4096      // word idx: epilogue O-combine scratch (reuses K buffers)
#define OST   68        // O-combine row stride (floats)

// barrier ids:
//  0: __syncthreads
//  1+g01        (128): K staged-visible / readers-done (2 rendezvous per iter)
//  3+g01        (128): V staged-visible / readers-done
//  5+g01*2+slot (256): P(slot) full   (S arrives, PV syncs)
//  9+g01*2+slot (256): P(slot) free   (PV arrives, S syncs from 2nd use)

// one-time fp16 scratch (prepass output)
__device__ __half g_kt[8192 * 128];      // K^T: [token][feature]
__device__ __half g_v[8 * 128 * 1024];   // V:   [batch][feature][token]

extern __shared__ float smdyn[];

__device__ __forceinline__ uint32_t smem_u32(const void* p) {
    uint32_t a;
    asm("{ .reg .u64 t; cvta.to.shared.u64 t, %1; cvt.u32.u64 %0, t; }" : "=r"(a) : "l"(p));
    return a;
}
__device__ __forceinline__ void bar_sync(int id, int cnt) {
    asm volatile("bar.sync %0, %1;" :: "r"(id), "r"(cnt) : "memory");
}
__device__ __forceinline__ void bar_arrive(int id, int cnt) {
    asm volatile("bar.arrive %0, %1;" :: "r"(id), "r"(cnt) : "memory");
}
__device__ __forceinline__ uint32_t h2bits(float a, float b) {
    __half2 h = __floats2half2_rn(a, b);
    return *reinterpret_cast<uint32_t*>(&h);
}
__device__ __forceinline__ float h2sum(uint32_t u) {
    __half2 h = *reinterpret_cast<__half2*>(&u);
    float2 f = __half22float2(h);
    return f.x + f.y;
}
__device__ __forceinline__ void sts128(uint32_t a, uint32_t u0, uint32_t u1,
                                       uint32_t u2, uint32_t u3) {
    asm volatile("st.shared.v4.b32 [%0], {%1,%2,%3,%4};"
                 :: "r"(a), "r"(u0), "r"(u1), "r"(u2), "r"(u3) : "memory");
}
__device__ __forceinline__ void sts32(uint32_t a, uint32_t u0) {
    asm volatile("st.shared.b32 [%0], %1;" :: "r"(a), "r"(u0) : "memory");
}
__device__ __forceinline__ void ldsm4(uint32_t r[4], uint32_t addr) {
    asm volatile("ldmatrix.sync.aligned.m8n8.x4.shared.b16 {%0,%1,%2,%3}, [%4];"
                 : "=r"(r[0]), "=r"(r[1]), "=r"(r[2]), "=r"(r[3]) : "r"(addr));
}
__device__ __forceinline__ void mma16(float c[4], const uint32_t a[4], const uint32_t b[2]) {
    asm volatile("mma.sync.aligned.m16n8k16.row.col.f32.f16.f16.f32 "
                 "{%0,%1,%2,%3}, {%4,%5,%6,%7}, {%8,%9}, {%0,%1,%2,%3};"
                 : "+f"(c[0]), "+f"(c[1]), "+f"(c[2]), "+f"(c[3])
                 : "r"(a[0]), "r"(a[1]), "r"(a[2]), "r"(a[3]),
                   "r"(b[0]), "r"(b[1]));
}
__device__ __forceinline__ void cp16h(uint32_t dst, const __half* src) {
    asm volatile("cp.async.cg.shared.global [%0], [%1], 16;" :: "r"(dst), "l"(src));
}
__device__ __forceinline__ void cp_commit() { asm volatile("cp.async.commit_group;"); }
__device__ __forceinline__ void cp_wait0()  { asm volatile("cp.async.wait_group 0;"); }

// ================= prepass: x fp32 -> fp16 scratch (K transposed) =================
__global__ void __launch_bounds__(256) prepass_kernel(const float* __restrict__ x) {
    const int tid  = blockIdx.x * 256 + threadIdx.x;   // 0..16383
    const int wid  = tid >> 5;                          // 0..511
    const int lane = threadIdx.x & 31;

#pragma unroll
    for (int i = 0; i < 8; i++) {
        int job = wid * 8 + i;
        int tb = job >> 4, fg = job & 15;
        int b = tb >> 5;
        int t = (tb & 31) * 32 + lane;
        const float* gp = x + (size_t)b * 393216u + (size_t)(128 + fg * 8) * 1024u + t;
        float f[8];
#pragma unroll
        for (int j = 0; j < 8; j++) f[j] = gp[(size_t)j * 1024];
        uint4 u;
        u.x = h2bits(f[0], f[1]); u.y = h2bits(f[2], f[3]);
        u.z = h2bits(f[4], f[5]); u.w = h2bits(f[6], f[7]);
        *(uint4*)(&g_kt[(size_t)((b * 1024 + t) * 128 + fg * 8)]) = u;
    }
#pragma unroll
    for (int i = 0; i < 8; i++) {
        int e = (i * 16384 + tid) * 8;
        int b = e >> 17;
        int r = e & 131071;
        const float* gp = x + (size_t)b * 393216u + r;
        float4 a0 = *(const float4*)gp;
        float4 a1 = *(const float4*)(gp + 4);
        uint4 u;
        u.x = h2bits(a0.x, a0.y); u.y = h2bits(a0.z, a0.w);
        u.z = h2bits(a1.x, a1.y); u.w = h2bits(a1.z, a1.w);
        *(uint4*)(&g_v[e]) = u;
    }
}

// ---- staging: cp.async fp16 scratch -> swizzled smem (4 warps per array) ----
__device__ __forceinline__ void stage_K_async(int kt, uint32_t skb, int pr, int lane) {
#pragma unroll
    for (int i = 0; i < 16; i++) {
        int id = pr * 512 + i * 32 + lane;      // 0..2047 16B-units
        int n = id >> 4, fg = id & 15;
        cp16h(skb + (uint32_t)(n * 256 + ((fg ^ (n & 7)) << 4)),
              g_kt + (size_t)((kt * 128 + n) * 128 + fg * 8));
    }
}
__device__ __forceinline__ void stage_V_async(int kt, uint32_t svb, int pr, int lane) {
    const int bv = kt >> 3, tof = (kt & 7) << 7;
#pragma unroll
    for (int i = 0; i < 16; i++) {
        int id = pr * 512 + i * 32 + lane;
        int v = id >> 4, u = id & 15;
        cp16h(svb + (uint32_t)(v * 256 + ((u ^ (v & 7)) << 4)),
              g_v + (size_t)((bv * 128 + v) * 1024 + tof + u * 8));
    }
}

__global__ void __launch_bounds__(512, 1)
conv_attn_kernel(const float* __restrict__ x, float* __restrict__ out) {
    const int tid  = threadIdx.x;
    const int lane = tid & 31;
    const int wid  = tid >> 5;
    const int g    = lane >> 2;
    const int t4   = lane & 3;
    const uint32_t sb = smem_u32(smdyn);
    float* smf = smdyn;

    const int g01  = wid >> 3;                 // 0 = group A (even kt), 1 = B (odd kt)
    const int w4   = wid & 3;
    const bool isS = (wid & 7) < 4;

    const int bq  = blockIdx.x >> 4;
    const int sq0 = (blockIdx.x & 15) << 6;
    const float* Qg = x + (size_t)bq * 393216u + 262144u + sq0;

    // ldmatrix per-lane decomposition
    const int rowoff  = ((lane >> 3) & 1) * 8 + (lane & 7);  // A rows
    const int selA    = lane >> 4;                           // A k-half
    const int rowoffB = (lane >> 4) * 8 + (lane & 7);        // B rows
    const int selB    = (lane >> 3) & 1;                     // B k-half
    const int sw      = lane & 7;

    const uint32_t sKg   = sb + (g01 ? KBB : KAB);
    const uint32_t sVg   = sb + (g01 ? VBB : VAB);
    const uint32_t sPgrp = sb + (g01 ? PB0B : PA0B);   // + slot<<14

    // ---- prologue: all warps stage Q; S warps cp K(g01); PV warps cp V(g01) ----
#pragma unroll
    for (int it = 0; it < 2; it++) {
        int job = wid + 16 * it;                 // 32 jobs: tg 0..1 x fg 0..15
        int tg = job >> 4, fg = job & 15;
        int m = tg * 32 + lane;
        const float* gp = Qg + (size_t)(fg * 8) * 1024 + m;
        float f[8];
#pragma unroll
        for (int j = 0; j < 8; j++) f[j] = gp[(size_t)j * 1024];
        uint32_t a = sb + QB + (uint32_t)(m * 256 + ((fg ^ (m & 7)) << 4));
        sts128(a, h2bits(f[0], f[1]), h2bits(f[2], f[3]),
                  h2bits(f[4], f[5]), h2bits(f[6], f[7]));
    }
    if (isS) { stage_K_async(g01, sKg, w4, lane); cp_commit(); }
    else     { stage_V_async(g01, sVg, w4, lane); cp_commit(); }
    __syncthreads();

    if (isS) {
        // ===== S warps (32x64 tiles): S = Q K^T, softmax -> P (2 slots) =====
        const int qrow = (w4 >> 1) * 32;
        const int scol = (w4 & 1) * 64;
        const uint32_t qa0 = sb + QB + (uint32_t)((qrow + rowoff) * 256);
        const uint32_t qa1 = qa0 + 16 * 256;
        const uint32_t kb  = sKg + (uint32_t)((scol + rowoffB) * 256);
        // lane-local rowsum partials; shfl-reduced ONCE in the epilogue
        float racc0[2] = {0.f, 0.f}, racc1[2] = {0.f, 0.f};

        for (int kt = g01; kt < NTILES; kt += 2) {
            const int slot = (kt >> 1) & 1;
            cp_wait0();
            bar_sync(1 + g01, 128);              // K(kt) visible (rendezvous 1)

            float c[2][8][4];
#pragma unroll
            for (int mt = 0; mt < 2; mt++)
#pragma unroll
                for (int nt = 0; nt < 8; nt++)
#pragma unroll
                    for (int r = 0; r < 4; r++) c[mt][nt][r] = 0.f;

#pragma unroll
            for (int ks = 0; ks < 8; ks++) {
                const uint32_t ua = (uint32_t)(((2 * ks + selA) ^ sw) << 4);
                const uint32_t ub = (uint32_t)(((2 * ks + selB) ^ sw) << 4);
                uint32_t a0[4], a1[4], b[4][4];
                ldsm4(a0, qa0 + ua);
                ldsm4(a1, qa1 + ua);
                ldsm4(b[0], kb + ub);
                ldsm4(b[1], kb + 16 * 256 + ub);
                ldsm4(b[2], kb + 32 * 256 + ub);
                ldsm4(b[3], kb + 48 * 256 + ub);
#pragma unroll
                for (int nb = 0; nb < 4; nb++) {
                    mma16(c[0][2 * nb],     a0, b[nb] + 0);
                    mma16(c[0][2 * nb + 1], a0, b[nb] + 2);
                    mma16(c[1][2 * nb],     a1, b[nb] + 0);
                    mma16(c[1][2 * nb + 1], a1, b[nb] + 2);
                }
            }
            bar_sync(1 + g01, 128);              // K readers done (rendezvous 2)
            if (kt + 2 < NTILES) { stage_K_async(kt + 2, sKg, w4, lane); cp_commit(); }

            if (kt >= 4) bar_sync(9 + g01 * 2 + slot, 256);  // P slot free (PV(kt-4) done)

            const uint32_t sPg = sPgrp + (uint32_t)(slot << 14);
#pragma unroll
            for (int mt = 0; mt < 2; mt++) {
                float s0 = 0.f, s1 = 0.f;
                const int row = qrow + mt * 16 + g;
#pragma unroll
                for (int nt = 0; nt < 8; nt++) {
                    float e0 = __expf(c[mt][nt][0] * SCALE);
                    float e1 = __expf(c[mt][nt][1] * SCALE);
                    float e2 = __expf(c[mt][nt][2] * SCALE);
                    float e3 = __expf(c[mt][nt][3] * SCALE);
                    uint32_t u01 = h2bits(e0, e1);
                    uint32_t u23 = h2bits(e2, e3);
                    s0 += h2sum(u01); s1 += h2sum(u23);
                    const int unit = (scol >> 3) + nt;
                    sts32(sPg + (uint32_t)(row * 256 + ((unit ^ g) << 4) + 4 * t4), u01);
                    sts32(sPg + (uint32_t)((row + 8) * 256 + ((unit ^ g) << 4) + 4 * t4), u23);
                }
                // no per-tile shfl: accumulate lane-local partials only
                racc0[mt] += s0; racc1[mt] += s1;
            }
            bar_arrive(5 + g01 * 2 + slot, 256); // P(kt) full
        }

        // ---- deferred rowsum reduction (once, off the loop critical path) ----
#pragma unroll
        for (int mt = 0; mt < 2; mt++) {
            racc0[mt] += __shfl_xor_sync(0xffffffffu, racc0[mt], 1);
            racc0[mt] += __shfl_xor_sync(0xffffffffu, racc0[mt], 2);
            racc1[mt] += __shfl_xor_sync(0xffffffffu, racc1[mt], 1);
            racc1[mt] += __shfl_xor_sync(0xffffffffu, racc1[mt], 2);
        }
        if (t4 == 0) {
#pragma unroll
            for (int mt = 0; mt < 2; mt++) {
                const int row = qrow + mt * 16 + g;
                smf[RS4W + row * 4 + g01 * 2 + (w4 & 1)]       = racc0[mt];
                smf[RS4W + (row + 8) * 4 + g01 * 2 + (w4 & 1)] = racc1[mt];
            }
        }
        __syncthreads();                          // epilogue join (1)
        if (tid < 64) {
            const float* r4 = smf + RS4W + tid * 4;
            smf[RSW + tid] = 1.0f / ((r4[0] + r4[1]) + (r4[2] + r4[3]));
        }
        __syncthreads();                          // epilogue join (2)
    } else {
        // ===== PV warps (64x32 tiles): O^T += V P^T over group's kt =====
        const int vrow = (w4 >> 1) * 64;
        const int mcol = (w4 & 1) * 32;
        const uint32_t va    = sVg + (uint32_t)((vrow + rowoff) * 256);
        const uint32_t pboff = (uint32_t)((mcol + rowoffB) * 256);

        float o[4][4][4];
#pragma unroll
        for (int a = 0; a < 4; a++)
#pragma unroll
            for (int b = 0; b < 4; b++)
#pragma unroll
                for (int r = 0; r < 4; r++) o[a][b][r] = 0.f;

        for (int kt = g01; kt < NTILES; kt += 2) {
            const int slot = (kt >> 1) & 1;
            bar_sync(5 + g01 * 2 + slot, 256);   // P(kt) full
            cp_wait0();
            bar_sync(3 + g01, 128);              // V(kt) visible (rendezvous 1)

            const uint32_t pbb = sPgrp + (uint32_t)(slot << 14) + pboff;
#pragma unroll
            for (int ks = 0; ks < 8; ks++) {
                const uint32_t ua = (uint32_t)(((2 * ks + selA) ^ sw) << 4);
                const uint32_t ub = (uint32_t)(((2 * ks + selB) ^ sw) << 4);
                uint32_t a[4][4], b0[4];
                ldsm4(a[0], va + ua);
                ldsm4(a[1], va + 16 * 256 + ua);
                ldsm4(a[2], va + 32 * 256 + ua);
                ldsm4(a[3], va + 48 * 256 + ua);
                ldsm4(b0, pbb + ub);
#pragma unroll
                for (int vt = 0; vt < 4; vt++) {
                    mma16(o[vt][0], a[vt], b0 + 0);
                    mma16(o[vt][1], a[vt], b0 + 2);
                }
                uint32_t b1[4];
                ldsm4(b1, pbb + 16 * 256 + ub);
#pragma unroll
                for (int vt = 0; vt < 4; vt++) {
                    mma16(o[vt][2], a[vt], b1 + 0);
                    mma16(o[vt][3], a[vt], b1 + 2);
                }
            }
            bar_arrive(9 + g01 * 2 + slot, 256); // P(kt) slot free
            bar_sync(3 + g01, 128);              // V readers done (rendezvous 2)
            if (kt + 2 < NTILES) { stage_V_async(kt + 2, sVg, w4, lane); cp_commit(); }
        }

        __syncthreads();                          // epilogue join (1)
        if (g01 == 0) {
            // group A: park partial O in smem (K buffers are dead now)
#pragma unroll
            for (int bn = 0; bn < 4; bn++) {
                const int m0 = mcol + bn * 8 + 2 * t4;
#pragma unroll
                for (int vt = 0; vt < 4; vt++) {
                    const int v = vrow + vt * 16 + g;
                    *(float2*)(smf + OCW + v * OST + m0) =
                        make_float2(o[vt][bn][0], o[vt][bn][1]);
                    *(float2*)(smf + OCW + (v + 8) * OST + m0) =
                        make_float2(o[vt][bn][2], o[vt][bn][3]);
                }
            }
        }
        __syncthreads();                          // epilogue join (2)
        if (g01 == 1) {
            // group B: combine + normalize + store
            float* Og = out + (size_t)bq * 131072u + sq0;
#pragma unroll
            for (int bn = 0; bn < 4; bn++) {
                const int m0 = mcol + bn * 8 + 2 * t4;
                const float i0 = smf[RSW + m0], i1 = smf[RSW + m0 + 1];
#pragma unroll
                for (int vt = 0; vt < 4; vt++) {
                    const int v = vrow + vt * 16 + g;
                    float2 a0 = *(const float2*)(smf + OCW + v * OST + m0);
                    float2 a1 = *(const float2*)(smf + OCW + (v + 8) * OST + m0);
                    *(float2*)(Og + (size_t)v * 1024 + m0) =
                        make_float2((a0.x + o[vt][bn][0]) * i0,
                                    (a0.y + o[vt][bn][1]) * i1);
                    *(float2*)(Og + (size_t)(v + 8) * 1024 + m0) =
                        make_float2((a1.x + o[vt][bn][2]) * i0,
                                    (a1.y + o[vt][bn][3]) * i1);
                }
            }
        }
    }
}

extern "C" void kernel_launch(void* const* d_in, const int* in_sizes, int n_in,
                              void* d_out, int out_size) {
    (void)in_sizes; (void)n_in; (void)out_size;
    const float* x = (const float*)d_in[0];
    float* out = (float*)d_out;
    cudaFuncSetAttribute(conv_attn_kernel,
                         cudaFuncAttributeMaxDynamicSharedMemorySize, SMEM_BYTES);
    prepass_kernel<<<64, 256>>>(x);
    conv_attn_kernel<<<128, 512, SMEM_BYTES>>>(x, out);
}